// round 17
// baseline (speedup 1.0000x reference)
#include <cuda_runtime.h>
#include <cuda_fp16.h>
#include <math.h>
#include <cstdint>

// Problem constants
#define B_ 4
#define N_ 2048
#define D_ 1024
#define H_ 16
#define HD_ 64
#define M_ (B_ * N_)          // 8192 rows
#define SCALE_ (1.0f / 64.0f)
#define NEG_ (-10000.0f)

// Scratch (static device globals — no runtime allocation allowed)
__device__ float2 g_cs[N_ * 32];                 // RoPE cos/sin table
__device__ __half g_x2[(size_t)M_ * D_];         // x  hi fp16
__device__ __half g_o2[(size_t)M_ * D_];         // attn out hi fp16
__device__ __half g_wqkv[(size_t)(3 * D_) * D_]; // Wq|Wk|Wv hi fp16
__device__ __half g_wo2[(size_t)D_ * D_];        // Wo hi fp16
__device__ __half g_qh[(size_t)M_ * D_];         // Q (pre-scaled by 1/64)
__device__ __half g_kh[(size_t)M_ * D_];
__device__ __half g_vth[(size_t)B_ * H_ * HD_ * N_];  // V fp16 [b,h,d,n]

__device__ __forceinline__ uint32_t smem_u32(const void* p) {
    uint32_t a;
    asm("{ .reg .u64 t; cvta.to.shared.u64 t, %1; cvt.u32.u64 %0, t; }"
        : "=r"(a) : "l"(p));
    return a;
}

#define CP16(dst, src) \
    asm volatile("cp.async.cg.shared.global [%0], [%1], 16;" :: "r"(dst), "l"(src))
#define LDMX4(r0, r1, r2, r3, addr) \
    asm volatile("ldmatrix.sync.aligned.m8n8.x4.shared.b16 {%0,%1,%2,%3}, [%4];" \
                 : "=r"(r0), "=r"(r1), "=r"(r2), "=r"(r3) : "r"(addr))
#define MMA4(dd, aa, b0, b1) \
    asm volatile("mma.sync.aligned.m16n8k16.row.col.f32.f16.f16.f32 " \
                 "{%0,%1,%2,%3}, {%4,%5,%6,%7}, {%8,%9}, {%0,%1,%2,%3};" \
                 : "+f"((dd)[0]), "+f"((dd)[1]), "+f"((dd)[2]), "+f"((dd)[3]) \
                 : "r"((aa)[0]), "r"((aa)[1]), "r"((aa)[2]), "r"((aa)[3]), \
                   "r"(b0), "r"(b1))

__device__ __forceinline__ uint32_t pack_h2(float x, float y) {
    __half2 h{__float2half(x), __float2half(y)};
    return *(uint32_t*)&h;
}

// ===========================================================================
// Unified fp16 prep: casts x + Wq/Wk/Wv (-> wqkv) + Wo (-> wo2) in one launch.
// ===========================================================================
__global__ void prep_cast_kernel(const float* __restrict__ x,
                                 const float* __restrict__ Wq,
                                 const float* __restrict__ Wk,
                                 const float* __restrict__ Wv,
                                 const float* __restrict__ Wo)
{
    int gid = blockIdx.x * blockDim.x + threadIdx.x;
    const int total = (M_ + 4 * D_) * (D_ / 4);
    if (gid >= total) return;
    int row = gid >> 8;
    int c8  = gid & 255;

    const float* src;
    __half* dst;
    if (row < M_) {
        src = x + (size_t)row * D_;
        dst = g_x2 + (size_t)row * D_;
    } else if (row < M_ + 3 * D_) {
        int wrow = row - M_;
        const float* w = (wrow < D_) ? Wq : (wrow < 2 * D_) ? Wk : Wv;
        src = w + (size_t)(wrow & (D_ - 1)) * D_;
        dst = g_wqkv + (size_t)wrow * D_;
    } else {
        int wrow = row - M_ - 3 * D_;
        src = Wo + (size_t)wrow * D_;
        dst = g_wo2 + (size_t)wrow * D_;
    }
    float4 xv = ((const float4*)src)[c8];
    ((uint32_t*)dst)[c8 * 2]     = pack_h2(xv.x, xv.y);
    ((uint32_t*)dst)[c8 * 2 + 1] = pack_h2(xv.z, xv.w);
}

// ===========================================================================
// RoPE cos/sin table build (DP trig, fast-math-immune)
// ===========================================================================
__global__ void build_cs_kernel()
{
    int gid = blockIdx.x * blockDim.x + threadIdx.x;
    if (gid >= N_ * 32) return;
    int pos = gid >> 5;
    int i   = gid & 31;
    float inv_f = (float)pow(10000.0, -(double)(2 * i) / 64.0);
    float ang   = (float)pos * inv_f;
    g_cs[gid] = make_float2((float)cos((double)ang), (float)sin((double)ang));
}

// ===========================================================================
// mma.sync fp16 GEMM, CTA 128x128, FOUR warps of 64x64 (128 threads),
// 2 CTA/SM, BK=64, ST=3, K=1024. 1.5x less LDSM traffic per MAC than the
// 8-warp 64x32 layout (each 64-row/col block loaded by 2 warps, not 4).
// emode 0: C = A@W^T + bias -> fp32 Cout.
// emode 1 (QKV fused): Q: RoPE + pre-scale -> qh ; K: RoPE -> kh ;
//                      V: fp16 transposed -> vth [b,h,d,n]
// ===========================================================================
#define BK 64
#define PITCH 72
#define TILE_ELEMS (128 * PITCH)
#define STAGE_ELEMS (2 * TILE_ELEMS)
#define ST 3
#define MM_SMEM (ST * STAGE_ELEMS * 2)

__global__ __launch_bounds__(128, 2) void mm_mma(
    const __half* __restrict__ A, const __half* __restrict__ Bw,
    const float* __restrict__ bias, float* __restrict__ Cout,
    __half* __restrict__ Qh, __half* __restrict__ Kh,
    __half* __restrict__ Vth, int emode)
{
    extern __shared__ __half dsm[];

    const int tid  = threadIdx.x;
    const int lane = tid & 31;
    const int wid  = tid >> 5;          // 0..3
    const int wm   = wid >> 1;          // 0..1 (64 rows)
    const int wn   = wid & 1;           // 0..1 (64 cols)
    const int bm   = blockIdx.y * 128;
    const int bn   = blockIdx.x * 128;

    const uint32_t base = smem_u32(dsm);
    const uint32_t fRow = (uint32_t)(lane & 15);
    const uint32_t fKof = (uint32_t)((lane >> 4) << 3);

    float d[4][8][4];
#pragma unroll
    for (int mi = 0; mi < 4; mi++)
#pragma unroll
        for (int ni = 0; ni < 8; ni++)
#pragma unroll
            for (int r = 0; r < 4; r++) d[mi][ni][r] = 0.0f;

    const int NC = D_ / BK;    // 16 chunks

    auto load_chunk = [&](int c, int stage) {
        uint32_t sA = base + (uint32_t)(stage * STAGE_ELEMS) * 2;
        uint32_t sB = sA + (uint32_t)TILE_ELEMS * 2;
#pragma unroll
        for (int t = 0; t < 8; t++) {
            int s = tid + t * 128;            // 0..1023
            int row = s >> 3, c16 = s & 7;
            uint32_t off = (uint32_t)(row * (PITCH * 2) + c16 * 16);
            const __half* gA = A  + (size_t)(bm + row) * D_ + c * BK + c16 * 8;
            const __half* gB = Bw + (size_t)(bn + row) * D_ + c * BK + c16 * 8;
            CP16(sA + off, gA);
            CP16(sB + off, gB);
        }
        asm volatile("cp.async.commit_group;");
    };

    load_chunk(0, 0);
    load_chunk(1, 1);

    for (int c = 0; c < NC; c++) {
        asm volatile("cp.async.wait_group 1;");
        __syncthreads();
        if (c + 2 < NC) load_chunk(c + 2, (c + 2) % ST);
        else asm volatile("cp.async.commit_group;");

        const int stage = c % ST;
        uint32_t sA = base + (uint32_t)(stage * STAGE_ELEMS) * 2;
        uint32_t sB = sA + (uint32_t)TILE_ELEMS * 2;

#pragma unroll
        for (int ks = 0; ks < 4; ks++) {
            uint32_t a[4][4], b[8][2];
#pragma unroll
            for (int mi = 0; mi < 4; mi++) {
                uint32_t addr = sA +
                    ((uint32_t)(wm * 64 + mi * 16) + fRow) * (PITCH * 2) +
                    ((uint32_t)(ks * 16) + fKof) * 2;
                LDMX4(a[mi][0], a[mi][1], a[mi][2], a[mi][3], addr);
            }
#pragma unroll
            for (int nj = 0; nj < 4; nj++) {       // n16 x4 -> two n8 frags
                uint32_t r0, r1, r2, r3;
                uint32_t addr = sB +
                    ((uint32_t)(wn * 64 + nj * 16) + fRow) * (PITCH * 2) +
                    ((uint32_t)(ks * 16) + fKof) * 2;
                LDMX4(r0, r1, r2, r3, addr);
                b[2 * nj][0] = r0;     b[2 * nj][1] = r2;
                b[2 * nj + 1][0] = r1; b[2 * nj + 1][1] = r3;
            }
#pragma unroll
            for (int mi = 0; mi < 4; mi++)
#pragma unroll
                for (int ni = 0; ni < 8; ni++)
                    MMA4(d[mi][ni], a[mi], b[ni][0], b[ni][1]);
        }
    }

    // ---- epilogue ----
    if (emode == 0) {
#pragma unroll
        for (int mi = 0; mi < 4; mi++) {
            int r0 = bm + wm * 64 + mi * 16 + (lane >> 2);
#pragma unroll
            for (int ni = 0; ni < 8; ni++) {
                int cc = bn + wn * 64 + ni * 8 + ((lane & 3) << 1);
                float b0 = bias[cc], b1 = bias[cc + 1];
                *(float2*)&Cout[(size_t)r0 * D_ + cc] =
                    make_float2(d[mi][ni][0] + b0, d[mi][ni][1] + b1);
                *(float2*)&Cout[(size_t)(r0 + 8) * D_ + cc] =
                    make_float2(d[mi][ni][2] + b0, d[mi][ni][3] + b1);
            }
        }
    } else {
        const int cbase = bn & 1023;
#pragma unroll
        for (int mi = 0; mi < 4; mi++) {
            int r0 = bm + wm * 64 + mi * 16 + (lane >> 2);
            int r1 = r0 + 8;
#pragma unroll
            for (int ni = 0; ni < 8; ni++) {
                int cc = cbase + wn * 64 + ni * 8 + ((lane & 3) << 1);
                if (bn >= 2048) {
                    // V: fp16, transposed into vth [b,h,d,n]
                    int hh = cc >> 6, dd = cc & 63;
                    int bb = r0 >> 11;
                    int n0 = r0 & (N_ - 1);
                    int n1 = r1 & (N_ - 1);
                    size_t hb = ((size_t)(bb * H_ + hh) * HD_ + dd) * N_;
                    Vth[hb + n0]       = __float2half(d[mi][ni][0]);
                    Vth[hb + N_ + n0]  = __float2half(d[mi][ni][1]);
                    Vth[hb + n1]       = __float2half(d[mi][ni][2]);
                    Vth[hb + N_ + n1]  = __float2half(d[mi][ni][3]);
                } else {                   // Q or K: RoPE on the (even, odd) pair
                    int i = (cc >> 1) & 31;
                    float2 cs0 = g_cs[(r0 & (N_ - 1)) * 32 + i];
                    float2 cs1 = g_cs[(r1 & (N_ - 1)) * 32 + i];
                    float x0 = d[mi][ni][0], y0 = d[mi][ni][1];
                    float x1 = d[mi][ni][2], y1 = d[mi][ni][3];
                    float a0 = fmaf(x0, cs0.x, -y0 * cs0.y);
                    float b0 = fmaf(y0, cs0.x,  x0 * cs0.y);
                    float a1 = fmaf(x1, cs1.x, -y1 * cs1.y);
                    float b1 = fmaf(y1, cs1.x,  x1 * cs1.y);
                    if (bn < 1024) {       // Q: pre-scale (exact pow2)
                        a0 *= SCALE_; b0 *= SCALE_;
                        a1 *= SCALE_; b1 *= SCALE_;
                        *(uint32_t*)&Qh[(size_t)r0 * D_ + cc] = pack_h2(a0, b0);
                        *(uint32_t*)&Qh[(size_t)r1 * D_ + cc] = pack_h2(a1, b1);
                    } else {
                        *(uint32_t*)&Kh[(size_t)r0 * D_ + cc] = pack_h2(a0, b0);
                        *(uint32_t*)&Kh[(size_t)r1 * D_ + cc] = pack_h2(a1, b1);
                    }
                }
            }
        }
    }
}

// ===========================================================================
// Tensor-core causal flash attention, fp16, no online max (unchanged R15).
// ===========================================================================
#define FP 72
#define FL_SMEM ((128 * FP + 2 * 64 * FP + 2 * 64 * FP) * 2)   // 55296 B

__global__ __launch_bounds__(256, 2) void flash_mma(
    const __half* __restrict__ qh, const __half* __restrict__ kh,
    const __half* __restrict__ vth, __half* __restrict__ o2)
{
    extern __shared__ __half sm[];
    __half* sQh = sm;                       // [128][FP]
    __half* sK  = sm + 128 * FP;            // [2 buf][64][FP]
    __half* sV  = sm + 128 * FP + 2 * 64 * FP;

    const int tid = threadIdx.x, lane = tid & 31, wid = tid >> 5;
    const int qb = (int)(gridDim.x - 1 - blockIdx.x);   // heavy tiles first
    const int h = blockIdx.y, b = blockIdx.z;
    const int qrow0 = qb * 128;

    {
#pragma unroll
        for (int i = 0; i < 4; i++) {
            int t = tid + i * 256;
            int r = t >> 3, s = t & 7;
            uint32_t dst = smem_u32(sQh + r * FP) + s * 16;
            const __half* src = qh +
                ((size_t)(b * N_ + qrow0 + r)) * D_ + h * HD_ + s * 8;
            CP16(dst, src);
        }
        asm volatile("cp.async.commit_group;");
    }

    auto load_kv = [&](int kb, int buf) {
#pragma unroll
        for (int i = 0; i < 4; i++) {
            int t = tid + i * 256;
            int tensor = t >> 9;
            int rem = t & 511;
            int r = rem >> 3, s = rem & 7;
            uint32_t dst;
            const __half* src;
            if (tensor == 0) {
                dst = smem_u32(sK + (buf * 64 + r) * FP) + s * 16;
                src = kh + ((size_t)(b * N_ + kb * 64 + r)) * D_ + h * HD_ + s * 8;
            } else {
                dst = smem_u32(sV + (buf * 64 + r) * FP) + s * 16;
                src = vth + ((size_t)((b * H_ + h) * HD_ + r)) * N_ + kb * 64 + s * 8;
            }
            CP16(dst, src);
        }
        asm volatile("cp.async.commit_group;");
    };

    load_kv(0, 0);
    asm volatile("cp.async.wait_group 0;");
    __syncthreads();

    uint32_t fqh[4][4];
    {
        uint32_t rowa = (uint32_t)(wid * 16 + (lane & 15));
        uint32_t cola = (uint32_t)(((lane >> 4) & 1) * 8);
        uint32_t bqh = smem_u32(sQh);
#pragma unroll
        for (int ks = 0; ks < 4; ks++) {
            uint32_t off = (rowa * FP + ks * 16 + cola) * 2;
            LDMX4(fqh[ks][0], fqh[ks][1], fqh[ks][2], fqh[ks][3], bqh + off);
        }
    }

    float l0 = 0.0f, l1 = 0.0f;
    float oacc[8][4];
#pragma unroll
    for (int f = 0; f < 8; f++)
#pragma unroll
        for (int r = 0; r < 4; r++) oacc[f][r] = 0.0f;

    const uint32_t rowb = (uint32_t)((lane & 7) + ((lane >> 4) & 1) * 8);
    const uint32_t colb8 = (uint32_t)(((lane >> 3) & 1) * 8);
    const int kbmax = 2 * qb + 1;

    for (int kb = 0; kb <= kbmax; kb++) {
        const int buf = kb & 1;
        if (kb) {
            asm volatile("cp.async.wait_group 0;");
            __syncthreads();
        }
        if (kb < kbmax) load_kv(kb + 1, buf ^ 1);

        float sacc[8][4];
#pragma unroll
        for (int f = 0; f < 8; f++)
#pragma unroll
            for (int r = 0; r < 4; r++) sacc[f][r] = 0.0f;

        uint32_t kbh = smem_u32(sK + buf * 64 * FP);
#pragma unroll
        for (int ks = 0; ks < 4; ks++) {
#pragma unroll
            for (int g = 0; g < 4; g++) {
                uint32_t b0, b1, b2, b3;
                uint32_t off = ((16 * g + rowb) * FP + ks * 16 + colb8) * 2;
                LDMX4(b0, b1, b2, b3, kbh + off);
                MMA4(sacc[2 * g],     fqh[ks], b0, b1);
                MMA4(sacc[2 * g + 1], fqh[ks], b2, b3);
            }
        }

        const int grow0 = qrow0 + wid * 16 + (lane >> 2);
        if (kb >= 2 * qb) {     // causal mask (diagonal tiles only)
#pragma unroll
            for (int f = 0; f < 8; f++) {
                int c = kb * 64 + f * 8 + 2 * (lane & 3);
                if (c     > grow0)     sacc[f][0] += NEG_;
                if (c + 1 > grow0)     sacc[f][1] += NEG_;
                if (c     > grow0 + 8) sacc[f][2] += NEG_;
                if (c + 1 > grow0 + 8) sacc[f][3] += NEG_;
            }
        }

        float rs0 = 0.0f, rs1 = 0.0f;
#pragma unroll
        for (int f = 0; f < 8; f++) {
            sacc[f][0] = __expf(sacc[f][0]);
            sacc[f][1] = __expf(sacc[f][1]);
            sacc[f][2] = __expf(sacc[f][2]);
            sacc[f][3] = __expf(sacc[f][3]);
            rs0 += sacc[f][0] + sacc[f][1];
            rs1 += sacc[f][2] + sacc[f][3];
        }
        rs0 += __shfl_xor_sync(0xffffffffu, rs0, 1);
        rs0 += __shfl_xor_sync(0xffffffffu, rs0, 2);
        rs1 += __shfl_xor_sync(0xffffffffu, rs1, 1);
        rs1 += __shfl_xor_sync(0xffffffffu, rs1, 2);
        l0 += rs0;
        l1 += rs1;

        uint32_t ph[4][4];
#pragma unroll
        for (int js = 0; js < 4; js++) {
            ph[js][0] = pack_h2(sacc[2 * js][0],     sacc[2 * js][1]);
            ph[js][1] = pack_h2(sacc[2 * js][2],     sacc[2 * js][3]);
            ph[js][2] = pack_h2(sacc[2 * js + 1][0], sacc[2 * js + 1][1]);
            ph[js][3] = pack_h2(sacc[2 * js + 1][2], sacc[2 * js + 1][3]);
        }

        uint32_t vbh = smem_u32(sV + buf * 64 * FP);
#pragma unroll
        for (int js = 0; js < 4; js++) {
#pragma unroll
            for (int g = 0; g < 4; g++) {
                uint32_t b0, b1, b2, b3;
                uint32_t off = ((16 * g + rowb) * FP + js * 16 + colb8) * 2;
                LDMX4(b0, b1, b2, b3, vbh + off);
                MMA4(oacc[2 * g],     ph[js], b0, b1);
                MMA4(oacc[2 * g + 1], ph[js], b2, b3);
            }
        }
        __syncthreads();
    }

    // epilogue: write hi fp16 into o2
    const int grow0 = qrow0 + wid * 16 + (lane >> 2);
    float inv0 = 1.0f / l0, inv1 = 1.0f / l1;
    size_t row0 = (size_t)(b * N_ + grow0) * D_;
    size_t row1 = row0 + 8 * D_;
    int colbase = h * HD_;
#pragma unroll
    for (int f = 0; f < 8; f++) {
        int dcol = colbase + f * 8 + 2 * (lane & 3);
        *(uint32_t*)&o2[row0 + dcol] = pack_h2(oacc[f][0] * inv0, oacc[f][1] * inv0);
        *(uint32_t*)&o2[row1 + dcol] = pack_h2(oacc[f][2] * inv1, oacc[f][3] * inv1);
    }
}

// ---------------------------------------------------------------------------
extern "C" void kernel_launch(void* const* d_in, const int* in_sizes, int n_in,
                              void* d_out, int out_size)
{
    const float* x  = (const float*)d_in[0];
    const float* Wq = (const float*)d_in[1];
    const float* Wk = (const float*)d_in[2];
    const float* Wv = (const float*)d_in[3];
    const float* Wo = (const float*)d_in[4];
    const float* bo = (const float*)d_in[5];
    float* out = (float*)d_out;

    __half *x2, *o2, *wqkv, *wo2, *qh, *kh, *vth;
    cudaGetSymbolAddress((void**)&x2, g_x2);
    cudaGetSymbolAddress((void**)&o2, g_o2);
    cudaGetSymbolAddress((void**)&wqkv, g_wqkv);
    cudaGetSymbolAddress((void**)&wo2, g_wo2);
    cudaGetSymbolAddress((void**)&qh, g_qh);
    cudaGetSymbolAddress((void**)&kh, g_kh);
    cudaGetSymbolAddress((void**)&vth, g_vth);

    cudaFuncSetAttribute(flash_mma, cudaFuncAttributeMaxDynamicSharedMemorySize,
                         (int)FL_SMEM);
    cudaFuncSetAttribute(mm_mma, cudaFuncAttributeMaxDynamicSharedMemorySize,
                         (int)MM_SMEM);

    build_cs_kernel<<<(N_ * 32 + 255) / 256, 256>>>();

    int prep_f4 = (M_ + 4 * D_) * (D_ / 4);
    prep_cast_kernel<<<(prep_f4 + 255) / 256, 256>>>(x, Wq, Wk, Wv, Wo);

    // QKV projection with fused RoPE (+Q pre-scale) + V-transpose epilogue
    dim3 qkvgrid(3 * D_ / 128, M_ / 128);  // (24, 64)
    mm_mma<<<qkvgrid, 128, MM_SMEM>>>(x2, wqkv, nullptr, nullptr,
                                      qh, kh, vth, 1);

    dim3 fgrid(N_ / 128, H_, B_);     // (16, 16, 4)
    flash_mma<<<fgrid, 256, FL_SMEM>>>(qh, kh, vth, o2);

    // Output projection with bias
    dim3 ogrid(D_ / 128, M_ / 128);   // (8, 64)
    mm_mma<<<ogrid, 128, MM_SMEM>>>(o2, wo2, bo, out,
                                    nullptr, nullptr, nullptr, 0);
}